// round 5
// baseline (speedup 1.0000x reference)
#include <cuda_runtime.h>

#define S_ 8
#define U_ 32
#define V_ 32
#define C_ 32
#define SU 256              // S_*U_
#define SV 256              // S_*V_
#define WSEG (S_*U_*V_)     // 8192 floats per segment
#define WS_STRIDE 514       // u64 (float2) per s-slice: 512 + 2 pad -> bank offset 4s
#define NBLOCKS 296         // 2 per SM on 148 SMs

// Thread = (row, s). Warp = 4 rows x 8 s. W (premultiplied by coef) lives in
// padded SMEM, broadcast-read conflict-free; x lives in registers. Row loop is
// barrier-free; __syncthreads only around per-segment W staging.
__global__ __launch_bounds__(256, 2)
void idxlin_kernel(const float* __restrict__ W,     // (C, S*U*V)
                   const float* __restrict__ X,     // (Z, S*U)
                   const int*   __restrict__ counts,
                   const float* __restrict__ coef,
                   float* __restrict__ out,         // (Z, S*V)
                   int Z)
{
    __shared__ __align__(16) unsigned long long w_sh[S_ * WS_STRIDE]; // 32.9 KB
    __shared__ int segStart[C_ + 1];

    const int tid = threadIdx.x;
    if (tid == 0) {
        int a = 0; segStart[0] = 0;
        #pragma unroll
        for (int c = 0; c < C_; ++c) { a += counts[c]; segStart[c + 1] = a; }
    }
    __syncthreads();

    const int lane = tid & 31;
    const int wid  = tid >> 5;
    const int s    = lane & 7;   // 8 s per warp -> W-LDS banks tile fully
    const int r4   = lane >> 3;  // 4 rows per warp (broadcast groups)

    const int rpb = (Z + NBLOCKS - 1) / NBLOCKS;
    const int lo  = blockIdx.x * rpb;
    const int hi  = min(lo + rpb, Z);
    if (lo >= Z) return;   // uniform per block

    int seg = 0;
    while (seg < C_ - 1 && segStart[seg + 1] <= lo) seg++;

    int cur = lo;
    while (cur < hi) {
        const int segTop = (seg < C_ - 1) ? segStart[seg + 1] : Z;
        const int e = min(segTop, hi);

        // ---- stage premultiplied W[seg] into padded SMEM (coalesced) ----
        __syncthreads();   // previous readers done with w_sh
        {
            const float4* wg = reinterpret_cast<const float4*>(W + (size_t)seg * WSEG);
            #pragma unroll
            for (int k = 0; k < WSEG / 4 / 256; ++k) {      // 8 iters
                const int idx4 = tid + 256 * k;
                float4 w = wg[idx4];
                const int ss  = idx4 >> 8;     // 256 float4 per s-slice
                const int rem = idx4 & 255;
                const float c0 = coef[ss];
                w.x *= c0; w.y *= c0; w.z *= c0; w.w *= c0;
                *reinterpret_cast<float4*>(&w_sh[ss * WS_STRIDE + rem * 2]) = w;
            }
        }
        __syncthreads();

        const unsigned long long* wbase = &w_sh[s * WS_STRIDE];

        // ---- barrier-free row loop ----
        for (int r = cur + wid * 4 + r4; r < e; r += 32) {
            const float4* xg = reinterpret_cast<const float4*>(
                X + (size_t)r * SU + s * U_);
            float4 x0 = xg[0], x1 = xg[1], x2 = xg[2], x3 = xg[3];
            float4 x4 = xg[4], x5 = xg[5], x6 = xg[6], x7 = xg[7];

            unsigned long long acc[16];
            #pragma unroll
            for (int j = 0; j < 16; ++j) acc[j] = 0ULL;

#define DO_U(xs, u) {                                                          \
    unsigned long long xx;                                                     \
    asm("mov.b64 %0, {%1, %1};" : "=l"(xx) : "f"(xs));                         \
    const ulonglong2* wr = reinterpret_cast<const ulonglong2*>(                \
        wbase + (u) * (V_ / 2));                                               \
    _Pragma("unroll")                                                          \
    for (int j8 = 0; j8 < 8; ++j8) {                                           \
        ulonglong2 ww = wr[j8];  /* LDS.128: 2 packed w-pairs */               \
        asm("fma.rn.f32x2 %0, %1, %2, %0;" : "+l"(acc[2*j8  ]) : "l"(xx), "l"(ww.x)); \
        asm("fma.rn.f32x2 %0, %1, %2, %0;" : "+l"(acc[2*j8+1]) : "l"(xx), "l"(ww.y)); \
    } }
#define DO_QUAD(xq, ub) DO_U((xq).x, ub) DO_U((xq).y, (ub)+1) \
                        DO_U((xq).z, (ub)+2) DO_U((xq).w, (ub)+3)

            DO_QUAD(x0,  0) DO_QUAD(x1,  4) DO_QUAD(x2,  8) DO_QUAD(x3, 12)
            DO_QUAD(x4, 16) DO_QUAD(x5, 20) DO_QUAD(x6, 24) DO_QUAD(x7, 28)
#undef DO_QUAD
#undef DO_U

            float4* og = reinterpret_cast<float4*>(out + (size_t)r * SV + s * V_);
            #pragma unroll
            for (int k = 0; k < 8; ++k) {
                float2 a = *reinterpret_cast<float2*>(&acc[2 * k]);
                float2 b = *reinterpret_cast<float2*>(&acc[2 * k + 1]);
                og[k] = make_float4(a.x, a.y, b.x, b.y);
            }
        }

        cur = e;
        seg++;
        if (seg >= C_ && cur < hi) break;  // safety if counts undersum
    }
}

extern "C" void kernel_launch(void* const* d_in, const int* in_sizes, int n_in,
                              void* d_out, int out_size) {
    const float* W      = (const float*)d_in[0];   // input1 (C, S*U*V)
    const float* X      = (const float*)d_in[1];   // input2 (Z, S*U)
    const int*   counts = (const int*)d_in[2];
    const float* coef   = (const float*)d_in[3];
    float* out = (float*)d_out;

    int Z = in_sizes[1] / SU;
    idxlin_kernel<<<NBLOCKS, 256>>>(W, X, counts, coef, out, Z);
}